// round 6
// baseline (speedup 1.0000x reference)
#include <cuda_runtime.h>
#include <cuda_fp16.h>
#include <mma.h>
#include <math.h>
#include <stdint.h>

using namespace nvcuda;

#define D_EMB 1024
#define NB 8
#define SQ 577
#define SK 13271
#define SKP 13312      // SK padded to 128
#define ROWP 640       // SQ padded to 128
#define SQP 640        // self-attn K padded
#define LNEPS 1e-5f

// ---------------- scratch (__device__ globals) ------------------------------
__device__ __half g_normX_h[(size_t)NB * SK * D_EMB];
__device__ float  g_normQ  [(size_t)NB * SQ * D_EMB];
__device__ __half g_normQ_h[(size_t)NB * SQ * D_EMB];
__device__ float  g_S      [(size_t)NB * ROWP * SKP];
__device__ __half g_P      [(size_t)NB * ROWP * SKP];
__device__ float  g_att    [(size_t)NB * ROWP * D_EMB];
__device__ float  g_cross  [(size_t)NB * SQ * D_EMB];
__device__ __half g_normC_h[(size_t)NB * SQ * D_EMB];
__device__ float  g_S2     [(size_t)NB * ROWP * SQP];
__device__ __half g_P2     [(size_t)NB * ROWP * SQP];
__device__ float  g_self   [(size_t)NB * ROWP * D_EMB];

// ---------------- reductions (blockDim == 256) ------------------------------
__device__ __forceinline__ float block_sum(float v, float* red) {
    #pragma unroll
    for (int o = 16; o > 0; o >>= 1) v += __shfl_xor_sync(0xffffffffu, v, o);
    int w = threadIdx.x >> 5;
    if ((threadIdx.x & 31) == 0) red[w] = v;
    __syncthreads();
    float s = 0.f;
    #pragma unroll
    for (int i = 0; i < 8; i++) s += red[i];
    __syncthreads();
    return s;
}
__device__ __forceinline__ float block_max(float v, float* red) {
    #pragma unroll
    for (int o = 16; o > 0; o >>= 1) v = fmaxf(v, __shfl_xor_sync(0xffffffffu, v, o));
    int w = threadIdx.x >> 5;
    if ((threadIdx.x & 31) == 0) red[w] = v;
    __syncthreads();
    float s = -INFINITY;
    #pragma unroll
    for (int i = 0; i < 8; i++) s = fmaxf(s, red[i]);
    __syncthreads();
    return s;
}

// ---------------- layernorm -> fp16 (optionally fp32 too) -------------------
__global__ void ln_kernel(const float* __restrict__ in, const float* __restrict__ w,
                          const float* __restrict__ b, __half* __restrict__ out_h,
                          float* __restrict__ out_f) {
    __shared__ float red[8];
    size_t row = blockIdx.x;
    float4 v = ((const float4*)(in + row * D_EMB))[threadIdx.x];
    float mean = block_sum(v.x + v.y + v.z + v.w, red) * (1.f / D_EMB);
    float dx = v.x - mean, dy = v.y - mean, dz = v.z - mean, dw = v.w - mean;
    float var = block_sum(dx*dx + dy*dy + dz*dz + dw*dw, red) * (1.f / D_EMB);
    float inv = rsqrtf(var + LNEPS);
    float4 w4 = ((const float4*)w)[threadIdx.x];
    float4 b4 = ((const float4*)b)[threadIdx.x];
    float ox = dx * inv * w4.x + b4.x;
    float oy = dy * inv * w4.y + b4.y;
    float oz = dz * inv * w4.z + b4.z;
    float ow = dw * inv * w4.w + b4.w;
    __half2 h0 = __floats2half2_rn(ox, oy);
    __half2 h1 = __floats2half2_rn(oz, ow);
    uint2 packed = { *(uint32_t*)&h0, *(uint32_t*)&h1 };
    ((uint2*)(out_h + row * D_EMB))[threadIdx.x] = packed;
    if (out_f) {
        float4 o = { ox, oy, oz, ow };
        ((float4*)(out_f + row * D_EMB))[threadIdx.x] = o;
    }
}

// ---------------- softmax: fp32 scores in -> fp16 probs out -----------------
__global__ void softmax_kernel(const float* __restrict__ S, __half* __restrict__ P,
                               int n, int np, int sq, int rowp) {
    extern __shared__ float buf[];
    __shared__ float red[8];
    int b = blockIdx.x / sq, r = blockIdx.x % sq;
    const float* src = S + ((size_t)b * rowp + r) * np;
    __half* dst = P + ((size_t)b * rowp + r) * np;
    float m = -INFINITY;
    for (int i = threadIdx.x; i < n; i += 256) { float v = src[i]; buf[i] = v; m = fmaxf(m, v); }
    m = block_max(m, red);
    float s = 0.f;
    for (int i = threadIdx.x; i < n; i += 256) { float e = __expf(buf[i] - m); buf[i] = e; s += e; }
    s = block_sum(s, red);
    float inv = 1.f / s;
    for (int i = threadIdx.x; i < n; i += 256) dst[i] = __float2half_rn(buf[i] * inv);
    for (int i = n + threadIdx.x; i < np; i += 256) dst[i] = __ushort_as_half(0);
}

// ---------------- cp.async helper -------------------------------------------
__device__ __forceinline__ void cp16(void* dst, const void* src, bool pred) {
    uint32_t d = (uint32_t)__cvta_generic_to_shared(dst);
    int sz = pred ? 16 : 0;
    asm volatile("cp.async.cg.shared.global [%0], [%1], 16, %2;\n" :: "r"(d), "l"(src), "r"(sz));
}

// ---------------- fp16 wmma GEMM, BM=128, 4-stage, 1 sync per k-tile --------
// C[m][n] = alpha * sum_k A[m][k] * Bop[k][n], A/B fp16, C fp32 (padded, direct store)
// TRANS_B=true : B is [N,K] row-major.  TRANS_B=false: B is [K,N] row-major.
// Grid: blockIdx.x = m-tile (FEW, fastest-varying -> co-scheduled m-tiles share
// the same B stripe through L2), blockIdx.y = n-tile, blockIdx.z = batch.
template <int WARPS_M, int WARPS_N, int BN, bool TRANS_B>
__global__ __launch_bounds__(WARPS_M * WARPS_N * 32)
void gemm_fp16(const __half* __restrict__ A, const __half* __restrict__ B, float* __restrict__ C,
               int Mreal, int Nreal, int K, int Kreal, int ldb_n, int ldc,
               size_t sA, size_t sB, size_t sC, float alpha) {
    constexpr int BM = 128;
    constexpr int T = WARPS_M * WARPS_N * 32;
    constexpr int WTM = BM / WARPS_M;
    constexpr int WTN = BN / WARPS_N;
    constexpr int FM = WTM / 16, FN = WTN / 16;
    constexpr int ALD = 40;                    // 32+8 halfs
    constexpr int ASZ = BM * ALD;
    constexpr int BLDN = BN + 8;
    constexpr int BSZ = TRANS_B ? BN * ALD : 32 * BLDN;
    constexpr int STAGE = ASZ + BSZ;           // halfs
    constexpr int NS = 4;                      // pipeline stages

    extern __shared__ __half smh[];

    A += blockIdx.z * sA;  B += blockIdx.z * sB;  C += blockIdx.z * sC;
    const int m0 = blockIdx.x * BM, n0 = blockIdx.y * BN;   // x = m (fast), y = n
    const int tid = threadIdx.x, warp = tid >> 5;
    const int wm = warp / WARPS_N, wn = warp % WARPS_N;

    wmma::fragment<wmma::accumulator, 16, 16, 16, float> acc[FM][FN];
    #pragma unroll
    for (int i = 0; i < FM; i++)
        #pragma unroll
        for (int j = 0; j < FN; j++) wmma::fill_fragment(acc[i][j], 0.f);

    auto load_tile = [&](int kt, int bufi) {
        const int k0 = kt * 32;
        __half* as = smh + bufi * STAGE;
        __half* bs = as + ASZ;
        #pragma unroll
        for (int i = 0; i < (BM * 4) / T; i++) {
            int idx = tid + i * T;
            int r = idx >> 2, v = (idx & 3) * 8;
            int gr = m0 + r;
            cp16(as + r * ALD + v, A + (size_t)gr * K + k0 + v, gr < Mreal);
        }
        if (TRANS_B) {
            #pragma unroll
            for (int i = 0; i < (BN * 4) / T; i++) {
                int idx = tid + i * T;
                int r = idx >> 2, v = (idx & 3) * 8;
                int gn = n0 + r;
                cp16(bs + r * ALD + v, B + (size_t)gn * K + k0 + v, gn < Nreal);
            }
        } else {
            #pragma unroll
            for (int i = 0; i < (32 * BN / 8) / T; i++) {
                int idx = tid + i * T;
                int kk = idx / (BN / 8), v = (idx % (BN / 8)) * 8;
                int gk = k0 + kk;
                cp16(bs + kk * BLDN + v, B + (size_t)gk * ldb_n + n0 + v, gk < Kreal);
            }
        }
        asm volatile("cp.async.commit_group;\n");
    };

    const int KT = K / 32;
    load_tile(0, 0);
    load_tile(1, 1);
    load_tile(2, 2);

    for (int kt = 0; kt < KT; kt++) {
        const int pend = KT - kt - 1;
        if (pend >= 2)      asm volatile("cp.async.wait_group 2;\n");
        else if (pend == 1) asm volatile("cp.async.wait_group 1;\n");
        else                asm volatile("cp.async.wait_group 0;\n");
        __syncthreads();
        if (kt + 3 < KT) load_tile(kt + 3, (kt + 3) % NS);

        const int bufi = kt % NS;
        __half* as = smh + bufi * STAGE;
        __half* bs = as + ASZ;
        #pragma unroll
        for (int ks = 0; ks < 2; ks++) {
            wmma::fragment<wmma::matrix_a, 16, 16, 16, __half, wmma::row_major> af[FM];
            #pragma unroll
            for (int i = 0; i < FM; i++)
                wmma::load_matrix_sync(af[i], as + (wm * WTM + i * 16) * ALD + ks * 16, ALD);
            if (TRANS_B) {
                #pragma unroll
                for (int j = 0; j < FN; j++) {
                    wmma::fragment<wmma::matrix_b, 16, 16, 16, __half, wmma::col_major> bf;
                    wmma::load_matrix_sync(bf, bs + (wn * WTN + j * 16) * ALD + ks * 16, ALD);
                    #pragma unroll
                    for (int i = 0; i < FM; i++) wmma::mma_sync(acc[i][j], af[i], bf, acc[i][j]);
                }
            } else {
                #pragma unroll
                for (int j = 0; j < FN; j++) {
                    wmma::fragment<wmma::matrix_b, 16, 16, 16, __half, wmma::row_major> bf;
                    wmma::load_matrix_sync(bf, bs + ks * 16 * BLDN + wn * WTN + j * 16, BLDN);
                    #pragma unroll
                    for (int i = 0; i < FM; i++) wmma::mma_sync(acc[i][j], af[i], bf, acc[i][j]);
                }
            }
        }
    }

    #pragma unroll
    for (int i = 0; i < FM; i++)
        #pragma unroll
        for (int j = 0; j < FN; j++) {
            #pragma unroll
            for (int e = 0; e < 8; e++) acc[i][j].x[e] *= alpha;
            int rg = m0 + wm * WTM + i * 16, cg = n0 + wn * WTN + j * 16;
            wmma::store_matrix_sync(C + (size_t)rg * ldc + cg, acc[i][j], ldc, wmma::mem_row_major);
        }
}

// ---------------- fused MLP (D->4->D, exact-erf GELU) -----------------------
__global__ void mlp_kernel(const float* __restrict__ att, const float* __restrict__ w1,
                           const float* __restrict__ b1, const float* __restrict__ w2,
                           const float* __restrict__ b2, float* __restrict__ out) {
    __shared__ float red[4][8];
    __shared__ float hh[4];
    int b = blockIdx.x / SQ, r = blockIdx.x % SQ;
    float4 v = ((const float4*)(att + ((size_t)b * ROWP + r) * D_EMB))[threadIdx.x];
    #pragma unroll
    for (int h = 0; h < 4; h++) {
        float4 w = ((const float4*)(w1 + (size_t)h * D_EMB))[threadIdx.x];
        float p = v.x * w.x + v.y * w.y + v.z * w.z + v.w * w.w;
        #pragma unroll
        for (int o = 16; o > 0; o >>= 1) p += __shfl_xor_sync(0xffffffffu, p, o);
        if ((threadIdx.x & 31) == 0) red[h][threadIdx.x >> 5] = p;
    }
    __syncthreads();
    if (threadIdx.x < 4) {
        float s = b1[threadIdx.x];
        #pragma unroll
        for (int i = 0; i < 8; i++) s += red[threadIdx.x][i];
        hh[threadIdx.x] = 0.5f * s * (1.f + erff(s * 0.70710678118654752f));
    }
    __syncthreads();
    float h0 = hh[0], h1 = hh[1], h2 = hh[2], h3 = hh[3];
    int d = threadIdx.x * 4;
    float4 wa = ((const float4*)w2)[d + 0];
    float4 wb = ((const float4*)w2)[d + 1];
    float4 wc = ((const float4*)w2)[d + 2];
    float4 wd = ((const float4*)w2)[d + 3];
    float4 o;
    o.x = h0 * wa.x + h1 * wa.y + h2 * wa.z + h3 * wa.w + b2[d + 0];
    o.y = h0 * wb.x + h1 * wb.y + h2 * wb.z + h3 * wb.w + b2[d + 1];
    o.z = h0 * wc.x + h1 * wc.y + h2 * wc.z + h3 * wc.w + b2[d + 2];
    o.w = h0 * wd.x + h1 * wd.y + h2 * wd.z + h3 * wd.w + b2[d + 3];
    ((float4*)(out + ((size_t)b * SQ + r) * D_EMB))[threadIdx.x] = o;
}

// ---------------- final combine ---------------------------------------------
__global__ void final_kernel(const float* __restrict__ normQ, const float* __restrict__ cross,
                             const float* __restrict__ selfa, const float* __restrict__ g1,
                             const float* __restrict__ g2, float* __restrict__ out) {
    int b = blockIdx.x / SQ, r = blockIdx.x % SQ;
    size_t ci = ((size_t)b * SQ + r) * 256 + threadIdx.x;
    size_t si = ((size_t)b * ROWP + r) * 256 + threadIdx.x;
    float4 q = ((const float4*)normQ)[ci];
    float4 c = ((const float4*)cross)[ci];
    float4 s = ((const float4*)selfa)[si];
    float4 a = ((const float4*)g1)[threadIdx.x];
    float4 bb = ((const float4*)g2)[threadIdx.x];
    float4 o;
    o.x = q.x + bb.x * (c.x + a.x * s.x);
    o.y = q.y + bb.y * (c.y + a.y * s.y);
    o.z = q.z + bb.z * (c.z + a.z * s.z);
    o.w = q.w + bb.w * (c.w + a.w * s.w);
    ((float4*)out)[ci] = o;
}

// ---------------- launch ------------------------------------------------------
extern "C" void kernel_launch(void* const* d_in, const int* in_sizes, int n_in,
                              void* d_out, int out_size) {
    const float* input_features = (const float*)d_in[0];
    const float* query_feature  = (const float*)d_in[1];
    const float* n1w = (const float*)d_in[2];
    const float* n1b = (const float*)d_in[3];
    const float* n2w = (const float*)d_in[4];
    const float* n2b = (const float*)d_in[5];
    const float* n3w = (const float*)d_in[6];
    const float* n3b = (const float*)d_in[7];
    const float* g1  = (const float*)d_in[8];
    const float* g2  = (const float*)d_in[9];
    const float* fc1w = (const float*)d_in[10];
    const float* fc1b = (const float*)d_in[11];
    const float* fc2w = (const float*)d_in[12];
    const float* fc2b = (const float*)d_in[13];

    __half *normX_h, *normQ_h, *normC_h, *P, *P2;
    float *normQ, *S, *att, *cross, *S2, *selfa;
    cudaGetSymbolAddress((void**)&normX_h, g_normX_h);
    cudaGetSymbolAddress((void**)&normQ,   g_normQ);
    cudaGetSymbolAddress((void**)&normQ_h, g_normQ_h);
    cudaGetSymbolAddress((void**)&S,       g_S);
    cudaGetSymbolAddress((void**)&P,       g_P);
    cudaGetSymbolAddress((void**)&att,     g_att);
    cudaGetSymbolAddress((void**)&cross,   g_cross);
    cudaGetSymbolAddress((void**)&normC_h, g_normC_h);
    cudaGetSymbolAddress((void**)&S2,      g_S2);
    cudaGetSymbolAddress((void**)&P2,      g_P2);
    cudaGetSymbolAddress((void**)&selfa,   g_self);

    const int SM_QK = 4 * (128 * 40 + 128 * 40) * 2;        // 81920
    const int SM_PV = 4 * (128 * 40 + 32 * 264) * 2;        // 108544
    cudaFuncSetAttribute((const void*)gemm_fp16<4, 2, 128, true>,  cudaFuncAttributeMaxDynamicSharedMemorySize, SM_QK);
    cudaFuncSetAttribute((const void*)gemm_fp16<2, 4, 256, false>, cudaFuncAttributeMaxDynamicSharedMemorySize, SM_PV);
    cudaFuncSetAttribute((const void*)softmax_kernel, cudaFuncAttributeMaxDynamicSharedMemorySize, SKP * 4);

    const float scale = 0.03125f;   // 1024^-0.5

    // 1) layernorms
    ln_kernel<<<NB * SK, 256>>>(input_features, n1w, n1b, normX_h, nullptr);
    ln_kernel<<<NB * SQ, 256>>>(query_feature,  n2w, n2b, normQ_h, normQ);

    // 2) cross attention  (grid: x = m-tiles (5, fast), y = n-tiles)
    gemm_fp16<4, 2, 128, true><<<dim3(ROWP / 128, SKP / 128, NB), 256, SM_QK>>>(
        normQ_h, normX_h, S, SQ, SK, D_EMB, D_EMB, 0, SKP,
        (size_t)SQ * D_EMB, (size_t)SK * D_EMB, (size_t)ROWP * SKP, scale);
    softmax_kernel<<<NB * SQ, 256, SKP * 4>>>(S, P, SK, SKP, SQ, ROWP);
    gemm_fp16<2, 4, 256, false><<<dim3(ROWP / 128, D_EMB / 256, NB), 256, SM_PV>>>(
        P, normX_h, att, SQ, D_EMB, SKP, SK, D_EMB, D_EMB,
        (size_t)ROWP * SKP, (size_t)SK * D_EMB, (size_t)ROWP * D_EMB, 1.f);

    // 3) MLP
    mlp_kernel<<<NB * SQ, 256>>>(att, fc1w, fc1b, fc2w, fc2b, cross);

    // 4) LN + self attention
    ln_kernel<<<NB * SQ, 256>>>(cross, n3w, n3b, normC_h, nullptr);
    gemm_fp16<4, 2, 128, true><<<dim3(ROWP / 128, SQP / 128, NB), 256, SM_QK>>>(
        normC_h, normC_h, S2, SQ, SQ, D_EMB, D_EMB, 0, SQP,
        (size_t)SQ * D_EMB, (size_t)SQ * D_EMB, (size_t)ROWP * SQP, scale);
    softmax_kernel<<<NB * SQ, 256, SQP * 4>>>(S2, P2, SQ, SQP, SQ, ROWP);
    gemm_fp16<2, 4, 256, false><<<dim3(ROWP / 128, D_EMB / 256, NB), 256, SM_PV>>>(
        P2, normC_h, selfa, SQ, D_EMB, SQP, SQ, D_EMB, D_EMB,
        (size_t)ROWP * SQP, (size_t)SQ * D_EMB, (size_t)ROWP * D_EMB, 1.f);

    // 5) combine
    final_kernel<<<NB * SQ, 256>>>(normQ, cross, selfa, g1, g2, (float*)d_out);
}

// round 8
// speedup vs baseline: 1.7926x; 1.7926x over previous
#include <cuda_runtime.h>
#include <cuda_fp16.h>
#include <mma.h>
#include <math.h>
#include <stdint.h>

using namespace nvcuda;

#define D_EMB 1024
#define NB 8
#define SQ 577
#define SK 13271
#define SKP 13312      // SK padded to 128
#define ROWP 640       // SQ padded to 128
#define SQP 640        // self-attn K padded
#define LNEPS 1e-5f

// ---------------- scratch (__device__ globals) ------------------------------
__device__ __half g_normX_h[(size_t)NB * SK * D_EMB];   // LN(input) fp16
__device__ float  g_xf     [(size_t)NB * SK * 4];       // normX @ fc1^T
__device__ float  g_normQ  [(size_t)NB * SQ * D_EMB];   // LN(query) fp32
__device__ __half g_normQ_h[(size_t)NB * SQ * D_EMB];
__device__ float  g_S      [(size_t)NB * ROWP * SKP];   // cross scores fp32
__device__ float  g_cross  [(size_t)NB * SQ * D_EMB];   // MLP out (fused), compact
__device__ __half g_normC_h[(size_t)NB * SQ * D_EMB];
__device__ float  g_S2     [(size_t)NB * ROWP * SQP];
__device__ __half g_P2     [(size_t)NB * ROWP * SQP];
__device__ float  g_self   [(size_t)NB * ROWP * D_EMB];

// ---------------- reductions (blockDim == 256) ------------------------------
__device__ __forceinline__ float block_sum(float v, float* red) {
    #pragma unroll
    for (int o = 16; o > 0; o >>= 1) v += __shfl_xor_sync(0xffffffffu, v, o);
    int w = threadIdx.x >> 5;
    if ((threadIdx.x & 31) == 0) red[w] = v;
    __syncthreads();
    float s = 0.f;
    #pragma unroll
    for (int i = 0; i < 8; i++) s += red[i];
    __syncthreads();
    return s;
}
__device__ __forceinline__ float block_max(float v, float* red) {
    #pragma unroll
    for (int o = 16; o > 0; o >>= 1) v = fmaxf(v, __shfl_xor_sync(0xffffffffu, v, o));
    int w = threadIdx.x >> 5;
    if ((threadIdx.x & 31) == 0) red[w] = v;
    __syncthreads();
    float s = -INFINITY;
    #pragma unroll
    for (int i = 0; i < 8; i++) s = fmaxf(s, red[i]);
    __syncthreads();
    return s;
}

// ---------------- layernorm -> fp16 (+ optional fp32, + optional Xf) --------
// If fc1 != nullptr, also writes xf[row*4+h] = dot(LN_out_row, fc1[h]).
__global__ void ln_kernel(const float* __restrict__ in, const float* __restrict__ w,
                          const float* __restrict__ b, __half* __restrict__ out_h,
                          float* __restrict__ out_f,
                          const float* __restrict__ fc1, float* __restrict__ xf) {
    __shared__ float red[8];
    __shared__ float red4[4][8];
    size_t row = blockIdx.x;
    float4 v = ((const float4*)(in + row * D_EMB))[threadIdx.x];
    float mean = block_sum(v.x + v.y + v.z + v.w, red) * (1.f / D_EMB);
    float dx = v.x - mean, dy = v.y - mean, dz = v.z - mean, dw = v.w - mean;
    float var = block_sum(dx*dx + dy*dy + dz*dz + dw*dw, red) * (1.f / D_EMB);
    float inv = rsqrtf(var + LNEPS);
    float4 w4 = ((const float4*)w)[threadIdx.x];
    float4 b4 = ((const float4*)b)[threadIdx.x];
    float ox = dx * inv * w4.x + b4.x;
    float oy = dy * inv * w4.y + b4.y;
    float oz = dz * inv * w4.z + b4.z;
    float ow = dw * inv * w4.w + b4.w;
    __half2 h0 = __floats2half2_rn(ox, oy);
    __half2 h1 = __floats2half2_rn(oz, ow);
    uint2 packed = { *(uint32_t*)&h0, *(uint32_t*)&h1 };
    ((uint2*)(out_h + row * D_EMB))[threadIdx.x] = packed;
    if (out_f) {
        float4 o = { ox, oy, oz, ow };
        ((float4*)(out_f + row * D_EMB))[threadIdx.x] = o;
    }
    if (fc1) {
        #pragma unroll
        for (int h = 0; h < 4; h++) {
            float4 f = ((const float4*)(fc1 + (size_t)h * D_EMB))[threadIdx.x];
            float p = ox * f.x + oy * f.y + oz * f.z + ow * f.w;
            #pragma unroll
            for (int o = 16; o > 0; o >>= 1) p += __shfl_xor_sync(0xffffffffu, p, o);
            if ((threadIdx.x & 31) == 0) red4[h][threadIdx.x >> 5] = p;
        }
        __syncthreads();
        if (threadIdx.x < 4) {
            float s = 0.f;
            #pragma unroll
            for (int i = 0; i < 8; i++) s += red4[threadIdx.x][i];
            xf[row * 4 + threadIdx.x] = s;
        }
    }
}

// ---------------- fused softmax + MLP (cross path) --------------------------
// Per row r: probs = softmax(S row); h = gelu(probs @ Xf + b1);
// cross row = h @ fc2^T + b2. Never materializes probs.
__global__ void softmax_mlp_kernel(const float* __restrict__ S, const float* __restrict__ xf,
                                   const float* __restrict__ b1, const float* __restrict__ fc2,
                                   const float* __restrict__ b2, float* __restrict__ cross) {
    extern __shared__ float buf[];
    __shared__ float red[8];
    int b = blockIdx.x / SQ, r = blockIdx.x % SQ;
    const float* src = S + ((size_t)b * ROWP + r) * SKP;
    const float4* xf4 = (const float4*)xf + (size_t)b * SK;
    float m = -INFINITY;
    for (int i = threadIdx.x; i < SK; i += 256) { float v = src[i]; buf[i] = v; m = fmaxf(m, v); }
    m = block_max(m, red);
    float s = 0.f, a0 = 0.f, a1 = 0.f, a2 = 0.f, a3 = 0.f;
    for (int i = threadIdx.x; i < SK; i += 256) {
        float e = __expf(buf[i] - m);
        s += e;
        float4 x = xf4[i];
        a0 += e * x.x; a1 += e * x.y; a2 += e * x.z; a3 += e * x.w;
    }
    s  = block_sum(s,  red);
    a0 = block_sum(a0, red);
    a1 = block_sum(a1, red);
    a2 = block_sum(a2, red);
    a3 = block_sum(a3, red);
    float inv = 1.f / s;
    float p0 = a0 * inv + b1[0];
    float p1 = a1 * inv + b1[1];
    float p2 = a2 * inv + b1[2];
    float p3 = a3 * inv + b1[3];
    const float k = 0.70710678118654752f;
    float h0 = 0.5f * p0 * (1.f + erff(p0 * k));
    float h1 = 0.5f * p1 * (1.f + erff(p1 * k));
    float h2 = 0.5f * p2 * (1.f + erff(p2 * k));
    float h3 = 0.5f * p3 * (1.f + erff(p3 * k));
    int d = threadIdx.x * 4;
    float* dst = cross + ((size_t)b * SQ + r) * D_EMB + d;
    float4 o;
    {
        float4 wv = ((const float4*)fc2)[d + 0];
        o.x = h0 * wv.x + h1 * wv.y + h2 * wv.z + h3 * wv.w + b2[d + 0];
    }
    {
        float4 wv = ((const float4*)fc2)[d + 1];
        o.y = h0 * wv.x + h1 * wv.y + h2 * wv.z + h3 * wv.w + b2[d + 1];
    }
    {
        float4 wv = ((const float4*)fc2)[d + 2];
        o.z = h0 * wv.x + h1 * wv.y + h2 * wv.z + h3 * wv.w + b2[d + 2];
    }
    {
        float4 wv = ((const float4*)fc2)[d + 3];
        o.w = h0 * wv.x + h1 * wv.y + h2 * wv.z + h3 * wv.w + b2[d + 3];
    }
    *(float4*)dst = o;
}

// ---------------- classic softmax (self path): fp32 in -> fp16 probs --------
__global__ void softmax_kernel(const float* __restrict__ S, __half* __restrict__ P,
                               int n, int np, int sq, int rowp) {
    extern __shared__ float buf[];
    __shared__ float red[8];
    int b = blockIdx.x / sq, r = blockIdx.x % sq;
    const float* src = S + ((size_t)b * rowp + r) * np;
    __half* dst = P + ((size_t)b * rowp + r) * np;
    float m = -INFINITY;
    for (int i = threadIdx.x; i < n; i += 256) { float v = src[i]; buf[i] = v; m = fmaxf(m, v); }
    m = block_max(m, red);
    float s = 0.f;
    for (int i = threadIdx.x; i < n; i += 256) { float e = __expf(buf[i] - m); buf[i] = e; s += e; }
    s = block_sum(s, red);
    float inv = 1.f / s;
    for (int i = threadIdx.x; i < n; i += 256) dst[i] = __float2half_rn(buf[i] * inv);
    for (int i = n + threadIdx.x; i < np; i += 256) dst[i] = __ushort_as_half(0);
}

// ---------------- cp.async helper -------------------------------------------
__device__ __forceinline__ void cp16(void* dst, const void* src, bool pred) {
    uint32_t d = (uint32_t)__cvta_generic_to_shared(dst);
    int sz = pred ? 16 : 0;
    asm volatile("cp.async.cg.shared.global [%0], [%1], 16, %2;\n" :: "r"(d), "l"(src), "r"(sz));
}

// ---------------- QK GEMM: NT fp16 wmma, 128x128x64, 3-stage ----------------
// C[m][n] = alpha * A[m][:] . B[n][:],  A [M,K], B [N,K] row-major fp16.
// grid: x = m-tile (fast), y = n-tile, z = batch.
#define QK_SMEM (3 * (128 * 72 + 128 * 72) * 2)
__global__ __launch_bounds__(256)
void gemm_qk(const __half* __restrict__ A, const __half* __restrict__ B, float* __restrict__ C,
             int Mreal, int Nreal, int K, int ldc,
             size_t sA, size_t sB, size_t sC, float alpha) {
    constexpr int ALD = 72;                     // 64+8 halfs
    constexpr int ASZ = 128 * ALD;
    constexpr int STAGE = 2 * ASZ;              // halfs

    extern __shared__ __half smh[];

    A += blockIdx.z * sA;  B += blockIdx.z * sB;  C += blockIdx.z * sC;
    const int m0 = blockIdx.x * 128, n0 = blockIdx.y * 128;
    const int tid = threadIdx.x, warp = tid >> 5;
    const int wm = warp >> 1, wn = warp & 1;    // 4x2 warps; 32m x 64n per warp

    wmma::fragment<wmma::accumulator, 16, 16, 16, float> acc[2][4];
    #pragma unroll
    for (int i = 0; i < 2; i++)
        #pragma unroll
        for (int j = 0; j < 4; j++) wmma::fill_fragment(acc[i][j], 0.f);

    auto load_tile = [&](int kt, int bufi) {
        const int k0 = kt * 64;
        __half* as = smh + bufi * STAGE;
        __half* bs = as + ASZ;
        #pragma unroll
        for (int i = 0; i < 4; i++) {           // A: 128 rows x 64 halfs
            int idx = tid + i * 256;
            int r = idx >> 3, v = (idx & 7) * 8;
            int gr = m0 + r;
            cp16(as + r * ALD + v, A + (size_t)gr * K + k0 + v, gr < Mreal);
        }
        #pragma unroll
        for (int i = 0; i < 4; i++) {           // B: 128 rows x 64 halfs
            int idx = tid + i * 256;
            int r = idx >> 3, v = (idx & 7) * 8;
            int gn = n0 + r;
            cp16(bs + r * ALD + v, B + (size_t)gn * K + k0 + v, gn < Nreal);
        }
        asm volatile("cp.async.commit_group;\n");
    };

    const int KT = K / 64;
    load_tile(0, 0);
    if (KT > 1) load_tile(1, 1);

    for (int kt = 0; kt < KT; kt++) {
        if (kt + 1 < KT) asm volatile("cp.async.wait_group 1;\n");
        else             asm volatile("cp.async.wait_group 0;\n");
        __syncthreads();
        if (kt + 2 < KT) load_tile(kt + 2, (kt + 2) % 3);

        __half* as = smh + (kt % 3) * STAGE;
        __half* bs = as + ASZ;
        #pragma unroll
        for (int ks = 0; ks < 4; ks++) {
            wmma::fragment<wmma::matrix_a, 16, 16, 16, __half, wmma::row_major> af[2];
            #pragma unroll
            for (int i = 0; i < 2; i++)
                wmma::load_matrix_sync(af[i], as + (wm * 32 + i * 16) * ALD + ks * 16, ALD);
            #pragma unroll
            for (int j = 0; j < 4; j++) {
                wmma::fragment<wmma::matrix_b, 16, 16, 16, __half, wmma::col_major> bf;
                wmma::load_matrix_sync(bf, bs + (wn * 64 + j * 16) * ALD + ks * 16, ALD);
                #pragma unroll
                for (int i = 0; i < 2; i++) wmma::mma_sync(acc[i][j], af[i], bf, acc[i][j]);
            }
        }
    }

    #pragma unroll
    for (int i = 0; i < 2; i++)
        #pragma unroll
        for (int j = 0; j < 4; j++) {
            #pragma unroll
            for (int e = 0; e < 8; e++) acc[i][j].x[e] *= alpha;
            int rg = m0 + wm * 32 + i * 16, cg = n0 + wn * 64 + j * 16;
            wmma::store_matrix_sync(C + (size_t)rg * ldc + cg, acc[i][j], ldc, wmma::mem_row_major);
        }
}

// ---------------- PV GEMM (self path): NN fp16 wmma, 128x256x32, 4-stage ----
// C[m][n] = sum_k A[m][k] * B[k][n]; A [M,K], B [K,N] row-major fp16.
#define PV_SMEM (4 * (128 * 40 + 32 * 264) * 2)
__global__ __launch_bounds__(256)
void gemm_pv(const __half* __restrict__ A, const __half* __restrict__ B, float* __restrict__ C,
             int Mreal, int K, int Kreal, int ldb_n, int ldc,
             size_t sA, size_t sB, size_t sC) {
    constexpr int BN = 256;
    constexpr int ALD = 40;
    constexpr int ASZ = 128 * ALD;
    constexpr int BLDN = BN + 8;
    constexpr int BSZ = 32 * BLDN;
    constexpr int STAGE = ASZ + BSZ;
    constexpr int NS = 4;

    extern __shared__ __half smh[];

    A += blockIdx.z * sA;  B += blockIdx.z * sB;  C += blockIdx.z * sC;
    const int m0 = blockIdx.x * 128, n0 = blockIdx.y * BN;
    const int tid = threadIdx.x, warp = tid >> 5;
    const int wm = warp >> 2, wn = warp & 3;    // 2x4 warps; 64m x 64n per warp

    wmma::fragment<wmma::accumulator, 16, 16, 16, float> acc[4][4];
    #pragma unroll
    for (int i = 0; i < 4; i++)
        #pragma unroll
        for (int j = 0; j < 4; j++) wmma::fill_fragment(acc[i][j], 0.f);

    auto load_tile = [&](int kt, int bufi) {
        const int k0 = kt * 32;
        __half* as = smh + bufi * STAGE;
        __half* bs = as + ASZ;
        #pragma unroll
        for (int i = 0; i < 2; i++) {
            int idx = tid + i * 256;
            int r = idx >> 2, v = (idx & 3) * 8;
            int gr = m0 + r;
            cp16(as + r * ALD + v, A + (size_t)gr * K + k0 + v, gr < Mreal);
        }
        #pragma unroll
        for (int i = 0; i < 4; i++) {
            int idx = tid + i * 256;
            int kk = idx >> 5, v = (idx & 31) * 8;
            int gk = k0 + kk;
            cp16(bs + kk * BLDN + v, B + (size_t)gk * ldb_n + n0 + v, gk < Kreal);
        }
        asm volatile("cp.async.commit_group;\n");
    };

    const int KT = K / 32;
    load_tile(0, 0);
    load_tile(1, 1);
    load_tile(2, 2);

    for (int kt = 0; kt < KT; kt++) {
        const int pend = KT - kt - 1;
        if (pend >= 2)      asm volatile("cp.async.wait_group 2;\n");
        else if (pend == 1) asm volatile("cp.async.wait_group 1;\n");
        else                asm volatile("cp.async.wait_group 0;\n");
        __syncthreads();
        if (kt + 3 < KT) load_tile(kt + 3, (kt + 3) % NS);

        __half* as = smh + (kt % NS) * STAGE;
        __half* bs = as + ASZ;
        #pragma unroll
        for (int ks = 0; ks < 2; ks++) {
            wmma::fragment<wmma::matrix_a, 16, 16, 16, __half, wmma::row_major> af[4];
            #pragma unroll
            for (int i = 0; i < 4; i++)
                wmma::load_matrix_sync(af[i], as + (wm * 64 + i * 16) * ALD + ks * 16, ALD);
            #pragma unroll
            for (int j = 0; j < 4; j++) {
                wmma::fragment<wmma::matrix_b, 16, 16, 16, __half, wmma::row_major> bf;
                wmma::load_matrix_sync(bf, bs + ks * 16 * BLDN + wn * 64 + j * 16, BLDN);
                #pragma unroll
                for (int i = 0; i < 4; i++) wmma::mma_sync(acc[i][j], af[i], bf, acc[i][j]);
            }
        }
    }

    #pragma unroll
    for (int i = 0; i < 4; i++)
        #pragma unroll
        for (int j = 0; j < 4; j++) {
            int rg = m0 + wm * 64 + i * 16, cg = n0 + wn * 64 + j * 16;
            wmma::store_matrix_sync(C + (size_t)rg * ldc + cg, acc[i][j], ldc, wmma::mem_row_major);
        }
}

// ---------------- final combine ---------------------------------------------
__global__ void final_kernel(const float* __restrict__ normQ, const float* __restrict__ cross,
                             const float* __restrict__ selfa, const float* __restrict__ g1,
                             const float* __restrict__ g2, float* __restrict__ out) {
    int b = blockIdx.x / SQ, r = blockIdx.x % SQ;
    size_t ci = ((size_t)b * SQ + r) * 256 + threadIdx.x;
    size_t si = ((size_t)b * ROWP + r) * 256 + threadIdx.x;
    float4 q = ((const float4*)normQ)[ci];
    float4 c = ((const float4*)cross)[ci];
    float4 s = ((const float4*)selfa)[si];
    float4 a = ((const float4*)g1)[threadIdx.x];
    float4 bb = ((const float4*)g2)[threadIdx.x];
    float4 o;
    o.x = q.x + bb.x * (c.x + a.x * s.x);
    o.y = q.y + bb.y * (c.y + a.y * s.y);
    o.z = q.z + bb.z * (c.z + a.z * s.z);
    o.w = q.w + bb.w * (c.w + a.w * s.w);
    ((float4*)out)[ci] = o;
}

// ---------------- launch ------------------------------------------------------
extern "C" void kernel_launch(void* const* d_in, const int* in_sizes, int n_in,
                              void* d_out, int out_size) {
    const float* input_features = (const float*)d_in[0];
    const float* query_feature  = (const float*)d_in[1];
    const float* n1w = (const float*)d_in[2];
    const float* n1b = (const float*)d_in[3];
    const float* n2w = (const float*)d_in[4];
    const float* n2b = (const float*)d_in[5];
    const float* n3w = (const float*)d_in[6];
    const float* n3b = (const float*)d_in[7];
    const float* g1  = (const float*)d_in[8];
    const float* g2  = (const float*)d_in[9];
    const float* fc1w = (const float*)d_in[10];
    const float* fc1b = (const float*)d_in[11];
    const float* fc2w = (const float*)d_in[12];
    const float* fc2b = (const float*)d_in[13];

    __half *normX_h, *normQ_h, *normC_h, *P2;
    float *xf, *normQ, *S, *cross, *S2, *selfa;
    cudaGetSymbolAddress((void**)&normX_h, g_normX_h);
    cudaGetSymbolAddress((void**)&xf,      g_xf);
    cudaGetSymbolAddress((void**)&normQ,   g_normQ);
    cudaGetSymbolAddress((void**)&normQ_h, g_normQ_h);
    cudaGetSymbolAddress((void**)&S,       g_S);
    cudaGetSymbolAddress((void**)&cross,   g_cross);
    cudaGetSymbolAddress((void**)&normC_h, g_normC_h);
    cudaGetSymbolAddress((void**)&S2,      g_S2);
    cudaGetSymbolAddress((void**)&P2,      g_P2);
    cudaGetSymbolAddress((void**)&selfa,   g_self);

    cudaFuncSetAttribute((const void*)gemm_qk, cudaFuncAttributeMaxDynamicSharedMemorySize, QK_SMEM);
    cudaFuncSetAttribute((const void*)gemm_pv, cudaFuncAttributeMaxDynamicSharedMemorySize, PV_SMEM);
    cudaFuncSetAttribute((const void*)softmax_mlp_kernel, cudaFuncAttributeMaxDynamicSharedMemorySize, SK * 4);
    cudaFuncSetAttribute((const void*)softmax_kernel, cudaFuncAttributeMaxDynamicSharedMemorySize, SQP * 4);

    const float scale = 0.03125f;   // 1024^-0.5

    // 1) layernorms (normX also emits Xf = LN(X) @ fc1^T, fused)
    ln_kernel<<<NB * SK, 256>>>(input_features, n1w, n1b, normX_h, nullptr, fc1w, xf);
    ln_kernel<<<NB * SQ, 256>>>(query_feature,  n2w, n2b, normQ_h, normQ, nullptr, nullptr);

    // 2) cross attention scores
    gemm_qk<<<dim3(ROWP / 128, SKP / 128, NB), 256, QK_SMEM>>>(
        normQ_h, normX_h, S, SQ, SK, D_EMB, SKP,
        (size_t)SQ * D_EMB, (size_t)SK * D_EMB, (size_t)ROWP * SKP, scale);

    // 3) fused softmax + MLP -> cross_attended (PV GEMM algebraically removed)
    softmax_mlp_kernel<<<NB * SQ, 256, SK * 4>>>(S, xf, fc1b, fc2w, fc2b, cross);

    // 4) LN(cross) + self attention
    ln_kernel<<<NB * SQ, 256>>>(cross, n3w, n3b, normC_h, nullptr, nullptr, nullptr);
    gemm_qk<<<dim3(ROWP / 128, SQP / 128, NB), 256, QK_SMEM>>>(
        normC_h, normC_h, S2, SQ, SQ, D_EMB, SQP,
        (size_t)SQ * D_EMB, (size_t)SQ * D_EMB, (size_t)ROWP * SQP, scale);
    softmax_kernel<<<NB * SQ, 256, SQP * 4>>>(S2, P2, SQ, SQP, SQ, ROWP);
    gemm_pv<<<dim3(ROWP / 128, D_EMB / 256, NB), 256, PV_SMEM>>>(
        P2, normC_h, selfa, SQ, SQP, SQ, D_EMB, D_EMB,
        (size_t)ROWP * SQP, (size_t)SQ * D_EMB, (size_t)ROWP * D_EMB);

    // 5) combine
    final_kernel<<<NB * SQ, 256>>>(normQ, cross, selfa, g1, g2, (float*)d_out);
}